// round 1
// baseline (speedup 1.0000x reference)
#include <cuda_runtime.h>

// Fixed problem shape (NuggetScorer_54400055771153)
#define BB 8
#define SS 4096
#define DD 2048
#define HH 128
#define MN 410            // ceil(4096 * 0.1)
#define MM (BB*SS)        // 32768 rows

#define ENC_SZ ((size_t)BB*MN*DD)   // 6,717,440
#define BMN (BB*MN)                 // 3,280

__device__ int g_idx[BB*MN];

// ---------------------------------------------------------------------------
// Kernel 1: fused score MLP.  scores[m] = gelu(A[m,:] @ W1 + b1) @ w2 + b2
// SGEMM tiling: BM=64 rows, BN=128 (=H, single N tile), BK=32.
// 256 threads, each computes a 4x8 micro-tile.
// ---------------------------------------------------------------------------
#define BM 64
#define BK 32
#define TM 4
#define TN 8

__global__ __launch_bounds__(256) void score_kernel(
    const float* __restrict__ A, const float* __restrict__ W1,
    const float* __restrict__ b1, const float* __restrict__ w2,
    const float* __restrict__ b2, float* __restrict__ scores)
{
    __shared__ float As[BK][BM + 1];   // transposed A tile, +1 pad
    __shared__ float Bs[BK][HH];       // W1 tile
    __shared__ float red[BM][17];      // per-row partial-score reduction

    const int tid = threadIdx.x;
    const int tx = tid & 15;           // N direction (16 x 8 = 128)
    const int ty = tid >> 4;           // M direction (16 x 4 = 64)
    const int row0 = blockIdx.x * BM;

    float acc[TM][TN];
#pragma unroll
    for (int i = 0; i < TM; i++)
#pragma unroll
        for (int j = 0; j < TN; j++) acc[i][j] = 0.f;

    for (int k0 = 0; k0 < DD; k0 += BK) {
        // Load A tile 64x32 (512 float4, 2 per thread), transpose into As[k][r]
#pragma unroll
        for (int l = 0; l < 2; l++) {
            int lin = tid + l * 256;       // 0..511
            int r   = lin >> 3;            // row within tile (32 floats = 8 f4/row)
            int kq  = lin & 7;
            float4 v = *(const float4*)(A + (size_t)(row0 + r) * DD + k0 + kq * 4);
            As[kq * 4 + 0][r] = v.x;
            As[kq * 4 + 1][r] = v.y;
            As[kq * 4 + 2][r] = v.z;
            As[kq * 4 + 3][r] = v.w;
        }
        // Load W1 tile 32x128 (1024 float4, 4 per thread)
#pragma unroll
        for (int l = 0; l < 4; l++) {
            int lin = tid + l * 256;       // 0..1023
            int r   = lin >> 5;            // k row (128 floats = 32 f4/row)
            int nq  = lin & 31;
            *(float4*)(&Bs[r][nq * 4]) =
                *(const float4*)(W1 + (size_t)(k0 + r) * HH + nq * 4);
        }
        __syncthreads();

#pragma unroll
        for (int k = 0; k < BK; k++) {
            float af[TM], bf[TN];
#pragma unroll
            for (int i = 0; i < TM; i++) af[i] = As[k][ty * TM + i];
            float4 bv0 = *(const float4*)(&Bs[k][tx * TN]);
            float4 bv1 = *(const float4*)(&Bs[k][tx * TN + 4]);
            bf[0] = bv0.x; bf[1] = bv0.y; bf[2] = bv0.z; bf[3] = bv0.w;
            bf[4] = bv1.x; bf[5] = bv1.y; bf[6] = bv1.z; bf[7] = bv1.w;
#pragma unroll
            for (int i = 0; i < TM; i++)
#pragma unroll
                for (int j = 0; j < TN; j++)
                    acc[i][j] = fmaf(af[i], bf[j], acc[i][j]);
        }
        __syncthreads();
    }

    // Epilogue: gelu(h + b1) * w2, partial sum over this thread's 8 columns
    float part[TM] = {0.f, 0.f, 0.f, 0.f};
#pragma unroll
    for (int j = 0; j < TN; j++) {
        int n = tx * TN + j;
        float b1v = __ldg(b1 + n);
        float w2v = __ldg(w2 + n);
#pragma unroll
        for (int i = 0; i < TM; i++) {
            float x = acc[i][j] + b1v;
            float g = 0.5f * x * (1.0f + erff(x * 0.7071067811865476f));
            part[i] = fmaf(g, w2v, part[i]);
        }
    }
#pragma unroll
    for (int i = 0; i < TM; i++) red[ty * TM + i][tx] = part[i];
    __syncthreads();

    if (tid < BM) {
        float s = b2[0];
#pragma unroll
        for (int t = 0; t < 16; t++) s += red[tid][t];
        scores[row0 + tid] = s;
    }
}

// ---------------------------------------------------------------------------
// Kernel 2: per-batch full bitonic sort (descending score, ascending index
// tie-break == stable argsort of -scores), n_token/n_nugget, top-MN outputs.
// ---------------------------------------------------------------------------
__global__ __launch_bounds__(1024) void topk_kernel(
    const float* __restrict__ scores, const int* __restrict__ mask,
    float* __restrict__ o_mask, float* __restrict__ o_ns,
    float* __restrict__ o_idx, int* __restrict__ idx_scr)
{
    __shared__ unsigned long long key[SS];
    __shared__ int sh_cnt;

    const int b = blockIdx.x;
    const int tid = threadIdx.x;
    if (tid == 0) sh_cnt = 0;
    __syncthreads();

    const float* srow = scores + (size_t)b * SS;
    const int*   mrow = mask   + (size_t)b * SS;

    int cnt = 0;
    for (int i = tid; i < SS; i += 1024) {
        float f = srow[i];
        unsigned u = __float_as_uint(f);
        u = (u & 0x80000000u) ? ~u : (u | 0x80000000u);  // total-order map
        // key: score (desc) major, index (asc) minor via (SS-1-i)
        key[i] = ((unsigned long long)u << 12) | (unsigned long long)(SS - 1 - i);
        cnt += mrow[i];
    }
#pragma unroll
    for (int o = 16; o > 0; o >>= 1) cnt += __shfl_down_sync(0xffffffffu, cnt, o);
    if ((tid & 31) == 0) atomicAdd(&sh_cnt, cnt);
    __syncthreads();

    // Bitonic sort, descending
    for (int k = 2; k <= SS; k <<= 1) {
        for (int j = k >> 1; j > 0; j >>= 1) {
            for (int i = tid; i < SS; i += 1024) {
                int l = i ^ j;
                if (l > i) {
                    unsigned long long a = key[i], c = key[l];
                    bool desc = ((i & k) == 0);
                    if (desc ? (a < c) : (a > c)) { key[i] = c; key[l] = a; }
                }
            }
            __syncthreads();
        }
    }

    int ntok = sh_cnt;
    int nn = (int)ceilf((float)ntok * 0.1f);   // match jnp fp32 ceil exactly
    nn = max(nn, 1);
    nn = min(nn, ntok);

    if (tid < MN) {
        unsigned long long kk = key[tid];
        int idx = (SS - 1) - (int)(kk & 0xFFFull);
        o_idx[b * MN + tid]  = (float)idx;
        o_ns[b * MN + tid]   = srow[idx];
        o_mask[b * MN + tid] = (tid < nn) ? 1.0f : 0.0f;
        idx_scr[b * MN + tid] = idx;
    }
}

// ---------------------------------------------------------------------------
// Kernel 3: gather enc rows. One block per (b, nugget) pair, 512 threads,
// each moves one float4 (512 * 4 = 2048 floats = D).
// ---------------------------------------------------------------------------
__global__ __launch_bounds__(512) void gather_kernel(
    const float* __restrict__ hidden, const int* __restrict__ idx,
    float* __restrict__ enc)
{
    int t = blockIdx.x;            // 0 .. BB*MN-1
    int b = t / MN;
    int s = idx[t];
    const float4* src = (const float4*)(hidden + ((size_t)b * SS + s) * DD);
    float4* dst = (float4*)(enc + (size_t)t * DD);
    dst[threadIdx.x] = src[threadIdx.x];
}

// ---------------------------------------------------------------------------
extern "C" void kernel_launch(void* const* d_in, const int* in_sizes, int n_in,
                              void* d_out, int out_size)
{
    const float* lhs  = (const float*)d_in[0];  // last_hidden_state (B,S,D)
    const float* hid  = (const float*)d_in[1];  // hidden_states     (B,S,D)
    const int*   mask = (const int*)  d_in[2];  // attention_mask    (B,S)
    const float* w1   = (const float*)d_in[3];  // (D,H)
    const float* b1   = (const float*)d_in[4];  // (H)
    const float* w2   = (const float*)d_in[5];  // (H,1)
    const float* b2   = (const float*)d_in[6];  // (1)

    float* out = (float*)d_out;
    // Output layout: enc | nugget_mask | nugget_scores | indices | scores
    float* o_enc    = out;
    float* o_mask   = out + ENC_SZ;
    float* o_ns     = o_mask + BMN;
    float* o_idx    = o_ns + BMN;
    float* o_scores = o_idx + BMN;

    int* idx_scr;
    cudaGetSymbolAddress((void**)&idx_scr, g_idx);

    score_kernel<<<MM / BM, 256>>>(lhs, w1, b1, w2, b2, o_scores);
    topk_kernel<<<BB, 1024>>>(o_scores, mask, o_mask, o_ns, o_idx, idx_scr);
    gather_kernel<<<BB * MN, 512>>>(hid, idx_scr, o_enc);
}

// round 3
// speedup vs baseline: 1.6343x; 1.6343x over previous
#include <cuda_runtime.h>

// Fixed problem shape (NuggetScorer_54400055771153)
#define BB 8
#define SS 4096
#define DD 2048
#define HH 128
#define MN 410            // ceil(4096 * 0.1)
#define MM (BB*SS)        // 32768 rows

#define ENC_SZ ((size_t)BB*MN*DD)   // 6,717,440
#define BMN (BB*MN)                 // 3,280

__device__ int g_idx[BB*MN];

typedef unsigned long long ull;

__device__ __forceinline__ ull pack2(float x, float y) {
    ull r; asm("mov.b64 %0,{%1,%2};" : "=l"(r) : "f"(x), "f"(y)); return r;
}
__device__ __forceinline__ void unpack2(ull v, float& x, float& y) {
    asm("mov.b64 {%0,%1},%2;" : "=f"(x), "=f"(y) : "l"(v));
}
__device__ __forceinline__ void ffma2(ull& d, ull a, ull b) {
    asm("fma.rn.f32x2 %0,%1,%2,%0;" : "+l"(d) : "l"(a), "l"(b));
}

// ---------------------------------------------------------------------------
// Kernel 1: fused score MLP.  scores[m] = gelu(A[m,:] @ W1 + b1) @ w2 + b2
// BM=128 rows, BN=128 (=H), BK=16. 256 threads, 8x8 micro-tile via FFMA2.
// Register-staged double buffering: LDG of tile k+1 in flight during compute.
// ---------------------------------------------------------------------------
#define BM 128
#define BK 16
#define ASTR 132          // padded stride for As rows

__global__ __launch_bounds__(256, 2) void score_kernel(
    const float* __restrict__ A, const float* __restrict__ W1,
    const float* __restrict__ bias1, const float* __restrict__ w2,
    const float* __restrict__ bias2, float* __restrict__ scores)
{
    __shared__ float As[BK][ASTR];   // transposed A tile: As[k][m]
    __shared__ float Bs[BK][HH];     // W1 tile: Bs[k][n]
    __shared__ float red[BM][17];    // per-row partial-score reduction

    const int tid = threadIdx.x;
    const int tx = tid & 15;         // n direction: cols tx*8 .. tx*8+7
    const int ty = tid >> 4;         // m direction: rows ty*8 .. ty*8+7
    const int row0 = blockIdx.x * BM;

    ull acc2[8][4];
#pragma unroll
    for (int i = 0; i < 8; i++)
#pragma unroll
        for (int j = 0; j < 4; j++) acc2[i][j] = 0ull;

    float4 sa[2], sb[2];

    // prologue: load tile 0 into registers
#pragma unroll
    for (int l = 0; l < 2; l++) {
        int lin = tid + l * 256;              // 0..511
        int r = lin >> 2, kq = lin & 3;       // A tile: 128 rows x 4 float4
        sa[l] = *(const float4*)(A + (size_t)(row0 + r) * DD + kq * 4);
        int rb = lin >> 5, nq = lin & 31;     // B tile: 16 rows x 32 float4
        sb[l] = *(const float4*)(W1 + (size_t)rb * HH + nq * 4);
    }

    const int NIT = DD / BK;                  // 128
    for (int it = 0; it < NIT; ++it) {
        // store staged tile into smem
#pragma unroll
        for (int l = 0; l < 2; l++) {
            int lin = tid + l * 256;
            int r = lin >> 2, kq = lin & 3;
            As[kq * 4 + 0][r] = sa[l].x;
            As[kq * 4 + 1][r] = sa[l].y;
            As[kq * 4 + 2][r] = sa[l].z;
            As[kq * 4 + 3][r] = sa[l].w;
            int rb = lin >> 5, nq = lin & 31;
            *(float4*)(&Bs[rb][nq * 4]) = sb[l];
        }
        __syncthreads();

        // issue LDG for next tile (in flight during compute below)
        if (it + 1 < NIT) {
            int k0 = (it + 1) * BK;
#pragma unroll
            for (int l = 0; l < 2; l++) {
                int lin = tid + l * 256;
                int r = lin >> 2, kq = lin & 3;
                sa[l] = *(const float4*)(A + (size_t)(row0 + r) * DD + k0 + kq * 4);
                int rb = lin >> 5, nq = lin & 31;
                sb[l] = *(const float4*)(W1 + (size_t)(k0 + rb) * HH + nq * 4);
            }
        }

        // compute 16 k-steps
#pragma unroll
        for (int k = 0; k < BK; k++) {
            ull b2v[4];
            const ull* bp = (const ull*)(&Bs[k][tx * 8]);
#pragma unroll
            for (int j = 0; j < 4; j++) b2v[j] = bp[j];
            float4 a0 = *(const float4*)(&As[k][ty * 8]);
            float4 a1 = *(const float4*)(&As[k][ty * 8 + 4]);
            float av[8] = {a0.x, a0.y, a0.z, a0.w, a1.x, a1.y, a1.z, a1.w};
#pragma unroll
            for (int i = 0; i < 8; i++) {
                ull a2 = pack2(av[i], av[i]);
#pragma unroll
                for (int j = 0; j < 4; j++) ffma2(acc2[i][j], a2, b2v[j]);
            }
        }
        __syncthreads();
    }

    // Epilogue: gelu(h + b1) * w2, partial sums over this thread's 8 columns
    float part[8] = {0.f, 0.f, 0.f, 0.f, 0.f, 0.f, 0.f, 0.f};
#pragma unroll
    for (int j2 = 0; j2 < 4; j2++) {
        int n = tx * 8 + j2 * 2;
        float b1v0 = __ldg(bias1 + n),     w2v0 = __ldg(w2 + n);
        float b1v1 = __ldg(bias1 + n + 1), w2v1 = __ldg(w2 + n + 1);
#pragma unroll
        for (int i = 0; i < 8; i++) {
            float x0, x1;
            unpack2(acc2[i][j2], x0, x1);
            x0 += b1v0; x1 += b1v1;
            float g0 = 0.5f * x0 * (1.0f + erff(x0 * 0.7071067811865476f));
            float g1 = 0.5f * x1 * (1.0f + erff(x1 * 0.7071067811865476f));
            part[i] = fmaf(g0, w2v0, fmaf(g1, w2v1, part[i]));
        }
    }
#pragma unroll
    for (int i = 0; i < 8; i++) red[ty * 8 + i][tx] = part[i];
    __syncthreads();

    if (tid < BM) {
        float s = bias2[0];
#pragma unroll
        for (int t = 0; t < 16; t++) s += red[tid][t];
        scores[row0 + tid] = s;
    }
}

// ---------------------------------------------------------------------------
// Kernel 2: per-batch full bitonic sort (descending score, ascending index
// tie-break == stable argsort of -scores), n_token/n_nugget, top-MN outputs.
// ---------------------------------------------------------------------------
__global__ __launch_bounds__(1024) void topk_kernel(
    const float* __restrict__ scores, const int* __restrict__ mask,
    float* __restrict__ o_mask, float* __restrict__ o_ns,
    float* __restrict__ o_idx, int* __restrict__ idx_scr)
{
    __shared__ unsigned long long key[SS];
    __shared__ int sh_cnt;

    const int b = blockIdx.x;
    const int tid = threadIdx.x;
    if (tid == 0) sh_cnt = 0;
    __syncthreads();

    const float* srow = scores + (size_t)b * SS;
    const int*   mrow = mask   + (size_t)b * SS;

    int cnt = 0;
    for (int i = tid; i < SS; i += 1024) {
        float f = srow[i];
        unsigned u = __float_as_uint(f);
        u = (u & 0x80000000u) ? ~u : (u | 0x80000000u);  // total-order map
        key[i] = ((unsigned long long)u << 12) | (unsigned long long)(SS - 1 - i);
        cnt += mrow[i];
    }
#pragma unroll
    for (int o = 16; o > 0; o >>= 1) cnt += __shfl_down_sync(0xffffffffu, cnt, o);
    if ((tid & 31) == 0) atomicAdd(&sh_cnt, cnt);
    __syncthreads();

    for (int k = 2; k <= SS; k <<= 1) {
        for (int j = k >> 1; j > 0; j >>= 1) {
            for (int i = tid; i < SS; i += 1024) {
                int l = i ^ j;
                if (l > i) {
                    unsigned long long a = key[i], c = key[l];
                    bool desc = ((i & k) == 0);
                    if (desc ? (a < c) : (a > c)) { key[i] = c; key[l] = a; }
                }
            }
            __syncthreads();
        }
    }

    int ntok = sh_cnt;
    int nn = (int)ceilf((float)ntok * 0.1f);
    nn = max(nn, 1);
    nn = min(nn, ntok);

    if (tid < MN) {
        unsigned long long kk = key[tid];
        int idx = (SS - 1) - (int)(kk & 0xFFFull);
        o_idx[b * MN + tid]  = (float)idx;
        o_ns[b * MN + tid]   = srow[idx];
        o_mask[b * MN + tid] = (tid < nn) ? 1.0f : 0.0f;
        idx_scr[b * MN + tid] = idx;
    }
}

// ---------------------------------------------------------------------------
// Kernel 3: gather enc rows.
// ---------------------------------------------------------------------------
__global__ __launch_bounds__(512) void gather_kernel(
    const float* __restrict__ hidden, const int* __restrict__ idx,
    float* __restrict__ enc)
{
    int t = blockIdx.x;
    int b = t / MN;
    int s = idx[t];
    const float4* src = (const float4*)(hidden + ((size_t)b * SS + s) * DD);
    float4* dst = (float4*)(enc + (size_t)t * DD);
    dst[threadIdx.x] = src[threadIdx.x];
}

// ---------------------------------------------------------------------------
extern "C" void kernel_launch(void* const* d_in, const int* in_sizes, int n_in,
                              void* d_out, int out_size)
{
    const float* lhs  = (const float*)d_in[0];
    const float* hid  = (const float*)d_in[1];
    const int*   mask = (const int*)  d_in[2];
    const float* w1   = (const float*)d_in[3];
    const float* b1   = (const float*)d_in[4];
    const float* w2   = (const float*)d_in[5];
    const float* b2   = (const float*)d_in[6];

    float* out = (float*)d_out;
    float* o_enc    = out;
    float* o_mask   = out + ENC_SZ;
    float* o_ns     = o_mask + BMN;
    float* o_idx    = o_ns + BMN;
    float* o_scores = o_idx + BMN;

    int* idx_scr;
    cudaGetSymbolAddress((void**)&idx_scr, g_idx);

    score_kernel<<<MM / BM, 256>>>(lhs, w1, b1, w2, b2, o_scores);
    topk_kernel<<<BB, 1024>>>(o_scores, mask, o_mask, o_ns, o_idx, idx_scr);
    gather_kernel<<<BB * MN, 512>>>(hid, idx_scr, o_enc);
}

// round 4
// speedup vs baseline: 1.6627x; 1.0174x over previous
#include <cuda_runtime.h>

// Fixed problem shape (NuggetScorer_54400055771153)
#define BB 8
#define SS 4096
#define DD 2048
#define HH 128
#define MN 410            // ceil(4096 * 0.1)
#define MM (BB*SS)        // 32768 rows

#define ENC_SZ ((size_t)BB*MN*DD)   // 6,717,440
#define BMN (BB*MN)                 // 3,280

__device__ int g_idx[BB*MN];

typedef unsigned long long ull;

__device__ __forceinline__ ull pack2(float x, float y) {
    ull r; asm("mov.b64 %0,{%1,%2};" : "=l"(r) : "f"(x), "f"(y)); return r;
}
__device__ __forceinline__ void unpack2(ull v, float& x, float& y) {
    asm("mov.b64 {%0,%1},%2;" : "=f"(x), "=f"(y) : "l"(v));
}
__device__ __forceinline__ void ffma2(ull& d, ull a, ull b) {
    asm("fma.rn.f32x2 %0,%1,%2,%0;" : "+l"(d) : "l"(a), "l"(b));
}

// ---------------------------------------------------------------------------
// Kernel 1: fused score MLP.  scores[m] = gelu(A[m,:] @ W1 + b1) @ w2 + b2
// BM=128, BN=128(=H), BK=16. 256 threads, 8x8 micro-tile via FFMA2.
// Ping-pong smem, ONE __syncthreads per tile; STS overlapped with compute.
// ---------------------------------------------------------------------------
#define BM 128
#define BK 16
#define ASTR 132          // padded stride for As rows (16B aligned: 132*4=528)

__global__ __launch_bounds__(256, 2) void score_kernel(
    const float* __restrict__ A, const float* __restrict__ W1,
    const float* __restrict__ bias1, const float* __restrict__ w2,
    const float* __restrict__ bias2, float* __restrict__ scores)
{
    __shared__ float As[2][BK][ASTR];   // transposed A tiles: As[buf][k][m]
    __shared__ float Bs[2][BK][HH];     // W1 tiles: Bs[buf][k][n]
    __shared__ float red[BM][17];       // per-row partial-score reduction

    const int tid = threadIdx.x;
    const int tx = tid & 15;            // n: cols tx*8 .. tx*8+7
    const int ty = tid >> 4;            // m: rows ty*8 .. ty*8+7
    const int row0 = blockIdx.x * BM;

    // per-thread load coordinates (computed once)
    const int ra0 = tid >> 2, ka0 = (tid & 3) * 4;               // A piece 0
    const int ra1 = (tid + 256) >> 2, ka1 = (tid & 3) * 4;       // A piece 1
    const int rb0 = tid >> 5, nb0 = (tid & 31) * 4;              // B piece 0
    const int rb1 = (tid + 256) >> 5, nb1 = (tid & 31) * 4;      // B piece 1

    ull acc2[8][4];
#pragma unroll
    for (int i = 0; i < 8; i++)
#pragma unroll
        for (int j = 0; j < 4; j++) acc2[i][j] = 0ull;

    float4 sa0, sa1, sb0, sb1;

    // prologue: tile 0 -> regs -> buf 0
    sa0 = *(const float4*)(A + (size_t)(row0 + ra0) * DD + ka0);
    sa1 = *(const float4*)(A + (size_t)(row0 + ra1) * DD + ka1);
    sb0 = *(const float4*)(W1 + (size_t)rb0 * HH + nb0);
    sb1 = *(const float4*)(W1 + (size_t)rb1 * HH + nb1);
    As[0][ka0 + 0][ra0] = sa0.x; As[0][ka0 + 1][ra0] = sa0.y;
    As[0][ka0 + 2][ra0] = sa0.z; As[0][ka0 + 3][ra0] = sa0.w;
    As[0][ka1 + 0][ra1] = sa1.x; As[0][ka1 + 1][ra1] = sa1.y;
    As[0][ka1 + 2][ra1] = sa1.z; As[0][ka1 + 3][ra1] = sa1.w;
    *(float4*)(&Bs[0][rb0][nb0]) = sb0;
    *(float4*)(&Bs[0][rb1][nb1]) = sb1;
    __syncthreads();

    const int NIT = DD / BK;                  // 128
    for (int it = 0; it < NIT; ++it) {
        const int cur = it & 1;

        // LDG next tile (in flight during compute)
        if (it + 1 < NIT) {
            int k0 = (it + 1) * BK;
            sa0 = *(const float4*)(A + (size_t)(row0 + ra0) * DD + k0 + ka0);
            sa1 = *(const float4*)(A + (size_t)(row0 + ra1) * DD + k0 + ka1);
            sb0 = *(const float4*)(W1 + (size_t)(k0 + rb0) * HH + nb0);
            sb1 = *(const float4*)(W1 + (size_t)(k0 + rb1) * HH + nb1);
        }

        // compute 16 k-steps from buf[cur]
#pragma unroll
        for (int k = 0; k < BK; k++) {
            ull b2v[4];
            const ull* bp = (const ull*)(&Bs[cur][k][tx * 8]);
#pragma unroll
            for (int j = 0; j < 4; j++) b2v[j] = bp[j];
            float4 a0 = *(const float4*)(&As[cur][k][ty * 8]);
            float4 a1 = *(const float4*)(&As[cur][k][ty * 8 + 4]);
            float av[8] = {a0.x, a0.y, a0.z, a0.w, a1.x, a1.y, a1.z, a1.w};
#pragma unroll
            for (int i = 0; i < 8; i++) {
                ull a2 = pack2(av[i], av[i]);
#pragma unroll
                for (int j = 0; j < 4; j++) ffma2(acc2[i][j], a2, b2v[j]);
            }
        }

        // STS next tile into the other buffer (overlaps tail of compute; safe:
        // every warp is past the previous sync, so nobody reads buf[cur^1])
        if (it + 1 < NIT) {
            const int nxt = cur ^ 1;
            As[nxt][ka0 + 0][ra0] = sa0.x; As[nxt][ka0 + 1][ra0] = sa0.y;
            As[nxt][ka0 + 2][ra0] = sa0.z; As[nxt][ka0 + 3][ra0] = sa0.w;
            As[nxt][ka1 + 0][ra1] = sa1.x; As[nxt][ka1 + 1][ra1] = sa1.y;
            As[nxt][ka1 + 2][ra1] = sa1.z; As[nxt][ka1 + 3][ra1] = sa1.w;
            *(float4*)(&Bs[nxt][rb0][nb0]) = sb0;
            *(float4*)(&Bs[nxt][rb1][nb1]) = sb1;
        }
        __syncthreads();
    }

    // Epilogue: gelu(h + b1) * w2, partial sums over this thread's 8 columns
    float part[8] = {0.f, 0.f, 0.f, 0.f, 0.f, 0.f, 0.f, 0.f};
#pragma unroll
    for (int j2 = 0; j2 < 4; j2++) {
        int n = tx * 8 + j2 * 2;
        float b1v0 = __ldg(bias1 + n),     w2v0 = __ldg(w2 + n);
        float b1v1 = __ldg(bias1 + n + 1), w2v1 = __ldg(w2 + n + 1);
#pragma unroll
        for (int i = 0; i < 8; i++) {
            float x0, x1;
            unpack2(acc2[i][j2], x0, x1);
            x0 += b1v0; x1 += b1v1;
            float g0 = 0.5f * x0 * (1.0f + erff(x0 * 0.7071067811865476f));
            float g1 = 0.5f * x1 * (1.0f + erff(x1 * 0.7071067811865476f));
            part[i] = fmaf(g0, w2v0, fmaf(g1, w2v1, part[i]));
        }
    }
#pragma unroll
    for (int i = 0; i < 8; i++) red[ty * 8 + i][tx] = part[i];
    __syncthreads();

    if (tid < BM) {
        float s = bias2[0];
#pragma unroll
        for (int t = 0; t < 16; t++) s += red[tid][t];
        scores[row0 + tid] = s;
    }
}

// ---------------------------------------------------------------------------
// Kernel 2: per-batch full bitonic sort (descending score, ascending index
// tie-break == stable argsort of -scores), n_token/n_nugget, top-MN outputs.
// ---------------------------------------------------------------------------
__global__ __launch_bounds__(1024) void topk_kernel(
    const float* __restrict__ scores, const int* __restrict__ mask,
    float* __restrict__ o_mask, float* __restrict__ o_ns,
    float* __restrict__ o_idx, int* __restrict__ idx_scr)
{
    __shared__ unsigned long long key[SS];
    __shared__ int sh_cnt;

    const int b = blockIdx.x;
    const int tid = threadIdx.x;
    if (tid == 0) sh_cnt = 0;
    __syncthreads();

    const float* srow = scores + (size_t)b * SS;
    const int*   mrow = mask   + (size_t)b * SS;

    int cnt = 0;
    for (int i = tid; i < SS; i += 1024) {
        float f = srow[i];
        unsigned u = __float_as_uint(f);
        u = (u & 0x80000000u) ? ~u : (u | 0x80000000u);  // total-order map
        key[i] = ((unsigned long long)u << 12) | (unsigned long long)(SS - 1 - i);
        cnt += mrow[i];
    }
#pragma unroll
    for (int o = 16; o > 0; o >>= 1) cnt += __shfl_down_sync(0xffffffffu, cnt, o);
    if ((tid & 31) == 0) atomicAdd(&sh_cnt, cnt);
    __syncthreads();

    for (int k = 2; k <= SS; k <<= 1) {
        for (int j = k >> 1; j > 0; j >>= 1) {
            for (int i = tid; i < SS; i += 1024) {
                int l = i ^ j;
                if (l > i) {
                    unsigned long long a = key[i], c = key[l];
                    bool desc = ((i & k) == 0);
                    if (desc ? (a < c) : (a > c)) { key[i] = c; key[l] = a; }
                }
            }
            __syncthreads();
        }
    }

    int ntok = sh_cnt;
    int nn = (int)ceilf((float)ntok * 0.1f);
    nn = max(nn, 1);
    nn = min(nn, ntok);

    if (tid < MN) {
        unsigned long long kk = key[tid];
        int idx = (SS - 1) - (int)(kk & 0xFFFull);
        o_idx[b * MN + tid]  = (float)idx;
        o_ns[b * MN + tid]   = srow[idx];
        o_mask[b * MN + tid] = (tid < nn) ? 1.0f : 0.0f;
        idx_scr[b * MN + tid] = idx;
    }
}

// ---------------------------------------------------------------------------
// Kernel 3: gather enc rows.
// ---------------------------------------------------------------------------
__global__ __launch_bounds__(512) void gather_kernel(
    const float* __restrict__ hidden, const int* __restrict__ idx,
    float* __restrict__ enc)
{
    int t = blockIdx.x;
    int b = t / MN;
    int s = idx[t];
    const float4* src = (const float4*)(hidden + ((size_t)b * SS + s) * DD);
    float4* dst = (float4*)(enc + (size_t)t * DD);
    dst[threadIdx.x] = src[threadIdx.x];
}

// ---------------------------------------------------------------------------
extern "C" void kernel_launch(void* const* d_in, const int* in_sizes, int n_in,
                              void* d_out, int out_size)
{
    const float* lhs  = (const float*)d_in[0];
    const float* hid  = (const float*)d_in[1];
    const int*   mask = (const int*)  d_in[2];
    const float* w1   = (const float*)d_in[3];
    const float* b1   = (const float*)d_in[4];
    const float* w2   = (const float*)d_in[5];
    const float* b2   = (const float*)d_in[6];

    float* out = (float*)d_out;
    float* o_enc    = out;
    float* o_mask   = out + ENC_SZ;
    float* o_ns     = o_mask + BMN;
    float* o_idx    = o_ns + BMN;
    float* o_scores = o_idx + BMN;

    int* idx_scr;
    cudaGetSymbolAddress((void**)&idx_scr, g_idx);

    score_kernel<<<MM / BM, 256>>>(lhs, w1, b1, w2, b2, o_scores);
    topk_kernel<<<BB, 1024>>>(o_scores, mask, o_mask, o_ns, o_idx, idx_scr);
    gather_kernel<<<BB * MN, 512>>>(hid, idx_scr, o_enc);
}